// round 1
// baseline (speedup 1.0000x reference)
#include <cuda_runtime.h>

#define B_    512
#define HW_   128
#define C1_   32
#define C2_   64

// Intermediate h: [512, 32, 64, 64] fp32 = 256 MB (static __device__, no alloc)
__device__ float g_h[(size_t)B_ * C1_ * 64 * 64];

// ---------------------------------------------------------------------------
// Kernel 1: Conv(3->32, k3, s1, p1) + bias + BN + ReLU + MaxPool2
//   in : crops [512, 3, 128, 128]
//   out: g_h   [512, 32, 64, 64]
// Grid (4, 4, 512): each block = one batch image, 16x16 pooled tile
//   -> 32x32 conv tile -> 34x34 input halo per channel.
// ---------------------------------------------------------------------------
__global__ void __launch_bounds__(256) conv1_fused(
    const float* __restrict__ crops,
    const float* __restrict__ w1, const float* __restrict__ b1,
    const float* __restrict__ g1, const float* __restrict__ be1,
    const float* __restrict__ m1, const float* __restrict__ v1)
{
    __shared__ float s_in[3][34][35];   // +1 col pad
    __shared__ float s_w[C1_ * 27];
    __shared__ float s_scale[C1_], s_bias[C1_];

    const int b  = blockIdx.z;
    const int cx0 = blockIdx.x * 32;    // conv-col origin of tile
    const int cy0 = blockIdx.y * 32;    // conv-row origin of tile
    const int t  = threadIdx.x;

    for (int i = t; i < C1_ * 27; i += 256) s_w[i] = w1[i];
    if (t < C1_) {
        float inv = g1[t] * rsqrtf(v1[t] + 1e-5f);
        s_scale[t] = inv;
        s_bias[t]  = be1[t] + (b1[t] - m1[t]) * inv;
    }

    const float* cb = crops + (size_t)b * 3 * HW_ * HW_;
    for (int i = t; i < 3 * 34 * 34; i += 256) {
        int ci = i / (34 * 34);
        int rem = i % (34 * 34);
        int r = rem / 34, c = rem % 34;
        int gr = cy0 - 1 + r, gc = cx0 - 1 + c;
        float v = 0.f;
        if (gr >= 0 && gr < HW_ && gc >= 0 && gc < HW_)
            v = cb[ci * HW_ * HW_ + gr * HW_ + gc];
        s_in[ci][r][c] = v;
    }
    __syncthreads();

    const int px = t & 15, py = t >> 4;   // pooled pixel in 16x16 tile

    // Register patch: 3 channels x 4x4 (covers the 2x2 conv window set)
    float p[3][4][4];
#pragma unroll
    for (int ci = 0; ci < 3; ci++)
#pragma unroll
        for (int r = 0; r < 4; r++)
#pragma unroll
            for (int c = 0; c < 4; c++)
                p[ci][r][c] = s_in[ci][2 * py + r][2 * px + c];

    float* hb = g_h + (size_t)b * C1_ * 64 * 64;
    const int oy = blockIdx.y * 16 + py;
    const int ox = blockIdx.x * 16 + px;

    for (int oc = 0; oc < C1_; oc++) {
        float a00 = 0.f, a01 = 0.f, a10 = 0.f, a11 = 0.f;
        const float* w = &s_w[oc * 27];
#pragma unroll
        for (int ci = 0; ci < 3; ci++)
#pragma unroll
            for (int ky = 0; ky < 3; ky++)
#pragma unroll
                for (int kx = 0; kx < 3; kx++) {
                    float wv = w[ci * 9 + ky * 3 + kx];
                    a00 = fmaf(p[ci][ky    ][kx    ], wv, a00);
                    a01 = fmaf(p[ci][ky    ][kx + 1], wv, a01);
                    a10 = fmaf(p[ci][ky + 1][kx    ], wv, a10);
                    a11 = fmaf(p[ci][ky + 1][kx + 1], wv, a11);
                }
        float sc = s_scale[oc], bi = s_bias[oc];
        float v0 = a00 * sc + bi, v1x = a01 * sc + bi;
        float v2 = a10 * sc + bi, v3  = a11 * sc + bi;
        float mv = fmaxf(fmaxf(v0, v1x), fmaxf(v2, v3));
        mv = fmaxf(mv, 0.f);   // ReLU commutes with max
        hb[oc * 64 * 64 + oy * 64 + ox] = mv;
    }
}

// ---------------------------------------------------------------------------
// Kernel 2: Conv(32->64, k3, s2, p1) + bias + BN + Sigmoid + MaxPool2
//   in : g_h  [512, 32, 64, 64]
//   out: feat [512, 64, 16, 16]
// Grid (2, 2, 512): each block = 8x8 pooled tile -> 16x16 conv tile
//   -> 33x33 input halo. Input channels processed in 8 chunks of 4.
// Thread t: pix = t&63 (8x8 pixel), grp = t>>6 (16 out-channels each).
// ---------------------------------------------------------------------------
__global__ void __launch_bounds__(256) conv2_fused(
    const float* __restrict__ w2, const float* __restrict__ b2,
    const float* __restrict__ g2, const float* __restrict__ be2,
    const float* __restrict__ m2, const float* __restrict__ v2,
    float* __restrict__ feat)
{
    __shared__ float s_in[4][33][34];   // +1 col pad
    __shared__ float s_w[C2_ * 4 * 9];  // 64 out-ch x 4 in-ch x 9
    __shared__ float s_scale[C2_], s_bias[C2_];

    const int b  = blockIdx.z;
    const int bx = blockIdx.x, by = blockIdx.y;
    const int t  = threadIdx.x;

    if (t < C2_) {
        float inv = g2[t] * rsqrtf(v2[t] + 1e-5f);
        s_scale[t] = inv;
        s_bias[t]  = be2[t] + (b2[t] - m2[t]) * inv;
    }

    const int pix = t & 63, grp = t >> 6;
    const int px = pix & 7, py = pix >> 3;

    float acc[16][2][2];
#pragma unroll
    for (int i = 0; i < 16; i++) {
        acc[i][0][0] = 0.f; acc[i][0][1] = 0.f;
        acc[i][1][0] = 0.f; acc[i][1][1] = 0.f;
    }

    const float* hb = g_h + (size_t)b * C1_ * 64 * 64;
    const int r0 = 32 * by - 1;   // global input-row of smem row 0
    const int c0 = 32 * bx - 1;

    for (int cc = 0; cc < 8; cc++) {          // 8 chunks of 4 input channels
        __syncthreads();                      // protect prior-iter smem reads
        // weights chunk: [oc][ci_local][k]
        for (int i = t; i < C2_ * 36; i += 256) {
            int oc = i / 36, rem = i % 36;
            int cil = rem / 9, k = rem % 9;
            s_w[i] = w2[oc * C1_ * 9 + (cc * 4 + cil) * 9 + k];
        }
        // input chunk: 4 x 33x33 with zero halo
        for (int i = t; i < 4 * 33 * 33; i += 256) {
            int cil = i / (33 * 33);
            int rem = i % (33 * 33);
            int r = rem / 33, c = rem % 33;
            int gr = r0 + r, gc = c0 + c;
            float v = 0.f;
            if (gr >= 0 && gr < 64 && gc >= 0 && gc < 64)
                v = hb[(cc * 4 + cil) * 64 * 64 + gr * 64 + gc];
            s_in[cil][r][c] = v;
        }
        __syncthreads();

#pragma unroll
        for (int cil = 0; cil < 4; cil++) {
            // 5x5 patch: smem rows 4py..4py+4, cols 4px..4px+4
            float p[5][5];
#pragma unroll
            for (int r = 0; r < 5; r++)
#pragma unroll
                for (int c = 0; c < 5; c++)
                    p[r][c] = s_in[cil][4 * py + r][4 * px + c];

#pragma unroll
            for (int oc = 0; oc < 16; oc++) {
                const float* w = &s_w[(grp * 16 + oc) * 36 + cil * 9];
#pragma unroll
                for (int ky = 0; ky < 3; ky++)
#pragma unroll
                    for (int kx = 0; kx < 3; kx++) {
                        float wv = w[ky * 3 + kx];
                        acc[oc][0][0] = fmaf(p[ky    ][kx    ], wv, acc[oc][0][0]);
                        acc[oc][0][1] = fmaf(p[ky    ][kx + 2], wv, acc[oc][0][1]);
                        acc[oc][1][0] = fmaf(p[ky + 2][kx    ], wv, acc[oc][1][0]);
                        acc[oc][1][1] = fmaf(p[ky + 2][kx + 2], wv, acc[oc][1][1]);
                    }
            }
        }
    }

    // Epilogue: affine -> max-pool -> sigmoid (sigmoid is monotone: 1 expf)
    const int oy = by * 8 + py, ox = bx * 8 + px;
    float* fb = feat + (size_t)b * C2_ * 16 * 16;
#pragma unroll
    for (int oc = 0; oc < 16; oc++) {
        int c = grp * 16 + oc;
        float sc = s_scale[c], bi = s_bias[c];
        float m = fmaxf(fmaxf(acc[oc][0][0], acc[oc][0][1]),
                        fmaxf(acc[oc][1][0], acc[oc][1][1]));
        float v = m * sc + bi;
        float sig = 1.f / (1.f + __expf(-v));
        fb[c * 256 + oy * 16 + ox] = sig;
    }
}

// ---------------------------------------------------------------------------
// Kernel 3: per-image mean over feat [64,16,16] -> scores + detected
// ---------------------------------------------------------------------------
__global__ void __launch_bounds__(256) score_reduce(
    const float* __restrict__ feat,
    float* __restrict__ scores,
    float* __restrict__ detected)
{
    const int b = blockIdx.x;
    const float* fb = feat + (size_t)b * 16384;
    float s = 0.f;
    for (int i = threadIdx.x; i < 16384; i += 256) s += fb[i];

    __shared__ float red[8];
#pragma unroll
    for (int o = 16; o > 0; o >>= 1) s += __shfl_down_sync(0xffffffffu, s, o);
    if ((threadIdx.x & 31) == 0) red[threadIdx.x >> 5] = s;
    __syncthreads();
    if (threadIdx.x < 8) {
        s = red[threadIdx.x];
#pragma unroll
        for (int o = 4; o > 0; o >>= 1) s += __shfl_down_sync(0xffu, s, o);
        if (threadIdx.x == 0) {
            float sc = s * (1.f / 16384.f);
            scores[b]   = sc;
            detected[b] = (sc >= 0.55f) ? 1.f : 0.f;
        }
    }
}

// ---------------------------------------------------------------------------
extern "C" void kernel_launch(void* const* d_in, const int* in_sizes, int n_in,
                              void* d_out, int out_size)
{
    const float* crops = (const float*)d_in[0];
    const float* w1  = (const float*)d_in[1];
    const float* b1  = (const float*)d_in[2];
    const float* g1  = (const float*)d_in[3];
    const float* be1 = (const float*)d_in[4];
    const float* m1  = (const float*)d_in[5];
    const float* v1  = (const float*)d_in[6];
    const float* w2  = (const float*)d_in[7];
    const float* b2  = (const float*)d_in[8];
    const float* g2  = (const float*)d_in[9];
    const float* be2 = (const float*)d_in[10];
    const float* m2  = (const float*)d_in[11];
    const float* v2  = (const float*)d_in[12];

    float* out      = (float*)d_out;
    float* feat     = out;                                   // 512*64*16*16
    float* scores   = out + (size_t)B_ * C2_ * 16 * 16;      // +512
    float* detected = scores + B_;                           // +512

    conv1_fused<<<dim3(4, 4, B_), 256>>>(crops, w1, b1, g1, be1, m1, v1);
    conv2_fused<<<dim3(2, 2, B_), 256>>>(w2, b2, g2, be2, m2, v2, feat);
    score_reduce<<<B_, 256>>>(feat, scores, detected);
}